// round 4
// baseline (speedup 1.0000x reference)
#include <cuda_runtime.h>

// VQ-VAE quantizer, bitwise-replicating the JAX/XLA-CPU fp32 reference:
//   x: [16, 256, 64, 64] f32   (d_in[0])
//   emb: [1024, 256] f32       (d_in[1])
//   out: [1 + 16*256*64*64] f32: out[0]=c_loss, out[1:]=quant_out (NCHW)
//
// Reference rounding model (CPU XLA, generic aarch64):
//   a_n = sum_c fl(x^2)  via 8 strided lane accumulators:
//         ((S0+S4)+(S2+S6)) + ((S1+S5)+(S3+S7)),  S_r = seq sum of c≡r (mod 8)
//   b_nk = strict sequential fp32 FMA chain over c ascending (Eigen gebp)
//   c_k  = same 8-lane pattern as a_n
//   d2   = fl( fl(a - fl(2*b)) + c ), argmin with first-index tie-break.

#define MT 128   // pixels per CTA
#define NT 128   // codes per tile
#define CC 32    // C chunk
#define THREADS 256
#define NUM_EMB 1024
#define EMB_DIM 256
#define HW 4096  // 64*64
#define NPIX 65536

__device__ double g_loss;
__device__ float g_enorm[NUM_EMB];
__device__ float g_xnorm[NPIX];

// 8-lane strided fp32 reduction matching LLVM-vectorized (VF=4, IC=2) fast-math
// reduce: lanewise acc0+acc1, then pairwise shuffle hsum.
__device__ __forceinline__ float reduce8_pattern(const float S[8]) {
    float t02 = __fadd_rn(__fadd_rn(S[0], S[4]), __fadd_rn(S[2], S[6]));
    float t13 = __fadd_rn(__fadd_rn(S[1], S[5]), __fadd_rn(S[3], S[7]));
    return __fadd_rn(t02, t13);
}

// Zero loss accumulator (graph replays!) and ||e_k||^2 with the 8-lane pattern.
__global__ void vq_init_kernel(const float* __restrict__ emb) {
    int k = blockIdx.x * blockDim.x + threadIdx.x;
    if (k == 0 && blockIdx.x == 0) g_loss = 0.0;
    if (k < NUM_EMB) {
        const float* row = emb + (size_t)k * EMB_DIM;
        float S[8];
#pragma unroll
        for (int r = 0; r < 8; r++) S[r] = 0.f;
        for (int c = 0; c < EMB_DIM; c += 8) {
#pragma unroll
            for (int r = 0; r < 8; r++) {
                float v = row[c + r];
                S[r] = __fadd_rn(S[r], __fmul_rn(v, v));
            }
        }
        g_enorm[k] = reduce8_pattern(S);
    }
}

// ||x_n||^2 per pixel with the 8-lane pattern. One thread per pixel; loads
// coalesced across threads (pixels contiguous, channel stride 4096).
__global__ __launch_bounds__(256)
void vq_xnorm_kernel(const float* __restrict__ x) {
    int p = blockIdx.x * 256 + threadIdx.x;  // 0..65535
    int b = p >> 12;
    int hw = p & (HW - 1);
    const float* xb = x + ((size_t)b * EMB_DIM) * HW + hw;
    float S[8];
#pragma unroll
    for (int r = 0; r < 8; r++) S[r] = 0.f;
    for (int c = 0; c < EMB_DIM; c += 8) {
#pragma unroll
        for (int r = 0; r < 8; r++) {
            float v = xb[(size_t)(c + r) * HW];
            S[r] = __fadd_rn(S[r], __fmul_rn(v, v));
        }
    }
    g_xnorm[p] = reduce8_pattern(S);
}

__global__ __launch_bounds__(THREADS)
void vq_main_kernel(const float* __restrict__ x,
                    const float* __restrict__ emb,
                    float* __restrict__ out) {
    __shared__ float xs[MT * (CC + 1)];   // [p][c], stride 33 (==1 mod 32)
    __shared__ float es[NT * (CC + 1)];   // [k][c], stride 33
    __shared__ int s_idx[MT];
    __shared__ double s_loss[THREADS / 32];

    const int tid = threadIdx.x;
    const int tx = tid & 15;   // k-dimension thread coord
    const int ty = tid >> 4;   // p-dimension thread coord

    const int pix0 = blockIdx.x * MT;    // global pixel offset
    const int b = pix0 >> 12;            // tile never crosses batch
    const int hw0 = pix0 & (HW - 1);
    const float* xbase = x + ((size_t)b * EMB_DIM) * HW + hw0;

    // Per-thread pixel norms (reference-rounded a_n)
    float a_p[8];
#pragma unroll
    for (int i = 0; i < 8; i++) a_p[i] = g_xnorm[pix0 + ty + 16 * i];

    float best[8];
    int bidx[8];
#pragma unroll
    for (int i = 0; i < 8; i++) { best[i] = 3.4e38f; bidx[i] = 0; }

    for (int kt = 0; kt < NUM_EMB; kt += NT) {
        float acc[8][8];
#pragma unroll
        for (int i = 0; i < 8; i++)
#pragma unroll
            for (int j = 0; j < 8; j++) acc[i][j] = 0.f;

        for (int cc = 0; cc < EMB_DIM; cc += CC) {
            __syncthreads();
#pragma unroll
            for (int it = 0; it < (MT * CC) / THREADS; it++) {
                int i = tid + it * THREADS;
                int p = i & (MT - 1);
                int cr = i >> 7;
                xs[p * (CC + 1) + cr] = xbase[(size_t)(cc + cr) * HW + p];
            }
#pragma unroll
            for (int it = 0; it < (NT * CC) / THREADS; it++) {
                int i = tid + it * THREADS;
                int c = i & (CC - 1);
                int k = i >> 5;
                es[k * (CC + 1) + c] = emb[(size_t)(kt + k) * EMB_DIM + cc + c];
            }
            __syncthreads();
            // Strict sequential FMA chain over c ascending for every (p,k):
            // exactly Eigen's gebp accumulation order.
#pragma unroll 8
            for (int c = 0; c < CC; c++) {
                float xv[8], ev[8];
#pragma unroll
                for (int i = 0; i < 8; i++) xv[i] = xs[(ty + 16 * i) * (CC + 1) + c];
#pragma unroll
                for (int j = 0; j < 8; j++) ev[j] = es[(tx + 16 * j) * (CC + 1) + c];
#pragma unroll
                for (int i = 0; i < 8; i++)
#pragma unroll
                    for (int j = 0; j < 8; j++)
                        acc[i][j] = fmaf(xv[i], ev[j], acc[i][j]);
            }
        }
        // Reference-rounded score: fl( fl(a - fl(2b)) + c ), k ascending per
        // thread, strict < => first-index tie-break within partition.
#pragma unroll
        for (int j = 0; j < 8; j++) {
            int k = kt + tx + 16 * j;
            float en = g_enorm[k];
#pragma unroll
            for (int i = 0; i < 8; i++) {
                float t = __fmul_rn(2.0f, acc[i][j]);
                float s = __fadd_rn(__fsub_rn(a_p[i], t), en);
                if (s < best[i]) { best[i] = s; bidx[i] = k; }
            }
        }
    }

    // Reduce (score, idx) across the 16 tx-threads per pixel; ties -> lower k.
#pragma unroll
    for (int i = 0; i < 8; i++) {
        float s = best[i];
        int k = bidx[i];
#pragma unroll
        for (int off = 8; off > 0; off >>= 1) {
            float so = __shfl_down_sync(0xffffffffu, s, off, 16);
            int ko = __shfl_down_sync(0xffffffffu, k, off, 16);
            if (so < s || (so == s && ko < k)) { s = so; k = ko; }
        }
        if (tx == 0) s_idx[ty + 16 * i] = k;
    }
    __syncthreads();

    // Writeback: coalesced NCHW stores; emb gather is L2-resident.
    float lsum = 0.f;
#pragma unroll 4
    for (int it = 0; it < (MT * EMB_DIM) / THREADS; it++) {
        int i = tid + it * THREADS;
        int p = i & (MT - 1);
        int c = i >> 7;
        int idx = s_idx[p];
        float q = __ldg(&emb[(size_t)idx * EMB_DIM + c]);
        float xv = xbase[(size_t)c * HW + p];
        out[1 + ((size_t)b * EMB_DIM + c) * HW + hw0 + p] = q;
        float d = q - xv;
        lsum = fmaf(d, d, lsum);
    }

    // Block loss reduction -> fp64 global accumulator
#pragma unroll
    for (int off = 16; off > 0; off >>= 1)
        lsum += __shfl_down_sync(0xffffffffu, lsum, off);
    if ((tid & 31) == 0) s_loss[tid >> 5] = (double)lsum;
    __syncthreads();
    if (tid == 0) {
        double t = 0.0;
#pragma unroll
        for (int w = 0; w < THREADS / 32; w++) t += s_loss[w];
        atomicAdd(&g_loss, t);
    }
}

__global__ void vq_finalize_kernel(float* __restrict__ out) {
    // c_loss = mse + COMM_COST * (mse * BETA) = mse * 1.0625
    out[0] = (float)(g_loss * (1.0625 / 16777216.0));
}

extern "C" void kernel_launch(void* const* d_in, const int* in_sizes, int n_in,
                              void* d_out, int out_size) {
    const float* x = (const float*)d_in[0];
    const float* emb = (const float*)d_in[1];
    float* out = (float*)d_out;

    vq_init_kernel<<<(NUM_EMB + 255) / 256, 256>>>(emb);
    vq_xnorm_kernel<<<NPIX / 256, 256>>>(x);
    vq_main_kernel<<<NPIX / MT, THREADS>>>(x, emb, out);
    vq_finalize_kernel<<<1, 1>>>(out);
}

// round 6
// speedup vs baseline: 1.0167x; 1.0167x over previous
#include <cuda_runtime.h>
#include <cstdint>

// VQ-VAE quantizer, bitwise-replicating the JAX/XLA-CPU fp32 reference,
// main GEMM on Blackwell packed fp32 (fma.rn.f32x2 -> SASS FFMA2, 2 FMA/issue).
//   x: [16, 256, 64, 64] f32   (d_in[0])
//   emb: [1024, 256] f32       (d_in[1])
//   out: [1 + 16*256*64*64] f32: out[0]=c_loss, out[1:]=quant_out (NCHW)

#define MT 128   // pixels per CTA
#define NT 128   // codes per tile
#define CC 32    // C chunk
#define THREADS 256
#define NUM_EMB 1024
#define EMB_DIM 256
#define HW 4096
#define NPIX 65536

#define FMA2(d, a, b, c) \
    asm("fma.rn.f32x2 %0, %1, %2, %3;" : "=l"(d) : "l"(a), "l"(b), "l"(c))
#define PACK2(d, lo, hi) \
    asm("mov.b64 %0, {%1, %2};" : "=l"(d) : "f"(lo), "f"(hi))
#define UNPACK2(lo, hi, s) \
    asm("mov.b64 {%0, %1}, %2;" : "=f"(lo), "=f"(hi) : "l"(s))

__device__ double g_loss;
__device__ float g_enorm[NUM_EMB];
__device__ float g_xnorm[NPIX];

// 8-lane strided fp32 reduction matching LLVM-vectorized (VF=4, IC=2)
// fast-math reduce on the reference CPU.
__device__ __forceinline__ float reduce8_pattern(const float S[8]) {
    float t02 = __fadd_rn(__fadd_rn(S[0], S[4]), __fadd_rn(S[2], S[6]));
    float t13 = __fadd_rn(__fadd_rn(S[1], S[5]), __fadd_rn(S[3], S[7]));
    return __fadd_rn(t02, t13);
}

__global__ void vq_init_kernel(const float* __restrict__ emb) {
    int k = blockIdx.x * blockDim.x + threadIdx.x;
    if (k == 0 && blockIdx.x == 0) g_loss = 0.0;
    if (k < NUM_EMB) {
        const float* row = emb + (size_t)k * EMB_DIM;
        float S[8];
#pragma unroll
        for (int r = 0; r < 8; r++) S[r] = 0.f;
        for (int c = 0; c < EMB_DIM; c += 8) {
#pragma unroll
            for (int r = 0; r < 8; r++) {
                float v = row[c + r];
                S[r] = __fadd_rn(S[r], __fmul_rn(v, v));
            }
        }
        g_enorm[k] = reduce8_pattern(S);
    }
}

__global__ __launch_bounds__(256)
void vq_xnorm_kernel(const float* __restrict__ x) {
    int p = blockIdx.x * 256 + threadIdx.x;
    int b = p >> 12;
    int hw = p & (HW - 1);
    const float* xb = x + ((size_t)b * EMB_DIM) * HW + hw;
    float S[8];
#pragma unroll
    for (int r = 0; r < 8; r++) S[r] = 0.f;
    for (int c = 0; c < EMB_DIM; c += 8) {
#pragma unroll
        for (int r = 0; r < 8; r++) {
            float v = xb[(size_t)(c + r) * HW];
            S[r] = __fadd_rn(S[r], __fmul_rn(v, v));
        }
    }
    g_xnorm[p] = reduce8_pattern(S);
}

__global__ __launch_bounds__(THREADS)
void vq_main_kernel(const float* __restrict__ x,
                    const float* __restrict__ emb,
                    float* __restrict__ out) {
    __shared__ float xs[CC * MT];         // [c][p], stride 128: float4-readable
    __shared__ float es[NT * (CC + 1)];   // [k][c], stride 33: conflict-free
    __shared__ int s_idx[MT];
    __shared__ double s_loss[THREADS / 32];

    const int tid = threadIdx.x;
    const int tx = tid & 15;   // k coord: handles codes tx + 16*j
    const int ty = tid >> 4;   // p coord: handles pixels 8*ty .. 8*ty+7

    const int pix0 = blockIdx.x * MT;
    const int b = pix0 >> 12;
    const int hw0 = pix0 & (HW - 1);
    const float* xbase = x + ((size_t)b * EMB_DIM) * HW + hw0;

    float a_p[8];
#pragma unroll
    for (int i = 0; i < 8; i++) a_p[i] = g_xnorm[pix0 + 8 * ty + i];

    float best[8];
    int bidx[8];
#pragma unroll
    for (int i = 0; i < 8; i++) { best[i] = 3.4e38f; bidx[i] = 0; }

    for (int kt = 0; kt < NUM_EMB; kt += NT) {
        uint64_t acc2[4][8];   // f32x2 accumulators: pixel pair (2i2,2i2+1) x code j
#pragma unroll
        for (int i2 = 0; i2 < 4; i2++)
#pragma unroll
            for (int j = 0; j < 8; j++) acc2[i2][j] = 0ull;

        for (int cc = 0; cc < EMB_DIM; cc += CC) {
            __syncthreads();
            // x chunk: global coalesced over p, smem [c][p] contiguous writes
#pragma unroll
            for (int it = 0; it < (MT * CC) / THREADS; it++) {
                int i = tid + it * THREADS;
                int p = i & (MT - 1);
                int cr = i >> 7;
                xs[cr * MT + p] = xbase[(size_t)(cc + cr) * HW + p];
            }
            // e chunk: global coalesced over c, smem [k][c] stride 33
#pragma unroll
            for (int it = 0; it < (NT * CC) / THREADS; it++) {
                int i = tid + it * THREADS;
                int c = i & (CC - 1);
                int k = i >> 5;
                es[k * (CC + 1) + c] = emb[(size_t)(kt + k) * EMB_DIM + cc + c];
            }
            __syncthreads();
            // Strict sequential fp32 FMA chain over c ascending per (p,k);
            // packed across the pixel axis (independent lanes => bitwise
            // identical to scalar fmaf chain).
#pragma unroll 4
            for (int c = 0; c < CC; c++) {
                float4 xa = *(const float4*)&xs[c * MT + 8 * ty];
                float4 xb4 = *(const float4*)&xs[c * MT + 8 * ty + 4];
                uint64_t xv2[4];
                PACK2(xv2[0], xa.x, xa.y);
                PACK2(xv2[1], xa.z, xa.w);
                PACK2(xv2[2], xb4.x, xb4.y);
                PACK2(xv2[3], xb4.z, xb4.w);
#pragma unroll
                for (int j = 0; j < 8; j++) {
                    float ev = es[(tx + 16 * j) * (CC + 1) + c];
                    uint64_t ev2;
                    PACK2(ev2, ev, ev);
#pragma unroll
                    for (int i2 = 0; i2 < 4; i2++)
                        FMA2(acc2[i2][j], xv2[i2], ev2, acc2[i2][j]);
                }
            }
        }
        // Reference-rounded score: fl( fl(a - fl(2b)) + c ), k ascending per
        // thread => strict < is first-index tie-break within the partition.
#pragma unroll
        for (int j = 0; j < 8; j++) {
            int k = kt + tx + 16 * j;
            float en = g_enorm[k];
#pragma unroll
            for (int i2 = 0; i2 < 4; i2++) {
                float blo, bhi;
                UNPACK2(blo, bhi, acc2[i2][j]);
                float s0 = __fadd_rn(__fsub_rn(a_p[2 * i2], __fmul_rn(2.0f, blo)), en);
                float s1 = __fadd_rn(__fsub_rn(a_p[2 * i2 + 1], __fmul_rn(2.0f, bhi)), en);
                if (s0 < best[2 * i2]) { best[2 * i2] = s0; bidx[2 * i2] = k; }
                if (s1 < best[2 * i2 + 1]) { best[2 * i2 + 1] = s1; bidx[2 * i2 + 1] = k; }
            }
        }
    }

    // Reduce (score, idx) across the 16 tx-threads per pixel; ties -> lower k.
#pragma unroll
    for (int i = 0; i < 8; i++) {
        float s = best[i];
        int k = bidx[i];
#pragma unroll
        for (int off = 8; off > 0; off >>= 1) {
            float so = __shfl_down_sync(0xffffffffu, s, off, 16);
            int ko = __shfl_down_sync(0xffffffffu, k, off, 16);
            if (so < s || (so == s && ko < k)) { s = so; k = ko; }
        }
        if (tx == 0) s_idx[8 * ty + i] = k;
    }
    __syncthreads();

    // Writeback: coalesced NCHW stores; emb gather is L2-resident.
    float lsum = 0.f;
#pragma unroll 4
    for (int it = 0; it < (MT * EMB_DIM) / THREADS; it++) {
        int i = tid + it * THREADS;
        int p = i & (MT - 1);
        int c = i >> 7;
        int idx = s_idx[p];
        float q = __ldg(&emb[(size_t)idx * EMB_DIM + c]);
        float xv = xbase[(size_t)c * HW + p];
        out[1 + ((size_t)b * EMB_DIM + c) * HW + hw0 + p] = q;
        float d = q - xv;
        lsum = fmaf(d, d, lsum);
    }

#pragma unroll
    for (int off = 16; off > 0; off >>= 1)
        lsum += __shfl_down_sync(0xffffffffu, lsum, off);
    if ((tid & 31) == 0) s_loss[tid >> 5] = (double)lsum;
    __syncthreads();
    if (tid == 0) {
        double t = 0.0;
#pragma unroll
        for (int w = 0; w < THREADS / 32; w++) t += s_loss[w];
        atomicAdd(&g_loss, t);
    }
}

__global__ void vq_finalize_kernel(float* __restrict__ out) {
    out[0] = (float)(g_loss * (1.0625 / 16777216.0));
}

extern "C" void kernel_launch(void* const* d_in, const int* in_sizes, int n_in,
                              void* d_out, int out_size) {
    const float* x = (const float*)d_in[0];
    const float* emb = (const float*)d_in[1];
    float* out = (float*)d_out;

    vq_init_kernel<<<(NUM_EMB + 255) / 256, 256>>>(emb);
    vq_xnorm_kernel<<<NPIX / 256, 256>>>(x);
    vq_main_kernel<<<NPIX / MT, THREADS>>>(x, emb, out);
    vq_finalize_kernel<<<1, 1>>>(out);
}

// round 7
// speedup vs baseline: 1.0181x; 1.0014x over previous
#include <cuda_runtime.h>
#include <cstdint>

// VQ-VAE quantizer, bitwise-replicating the JAX/XLA-CPU fp32 reference,
// main GEMM on Blackwell packed fp32 (fma.rn.f32x2 -> SASS FFMA2, 2 FMA/issue).
//   x: [16, 256, 64, 64] f32   (d_in[0])
//   emb: [1024, 256] f32       (d_in[1])
//   out: [1 + 16*256*64*64] f32: out[0]=c_loss, out[1:]=quant_out (NCHW)

#define MT 128   // pixels per CTA
#define NT 128   // codes per tile
#define CC 32    // C chunk
#define THREADS 256
#define NUM_EMB 1024
#define EMB_DIM 256
#define HW 4096
#define NPIX 65536

#define FMA2(d, a, b, c) \
    asm("fma.rn.f32x2 %0, %1, %2, %3;" : "=l"(d) : "l"(a), "l"(b), "l"(c))
#define PACK2(d, lo, hi) \
    asm("mov.b64 %0, {%1, %2};" : "=l"(d) : "f"(lo), "f"(hi))
#define UNPACK2(lo, hi, s) \
    asm("mov.b64 {%0, %1}, %2;" : "=f"(lo), "=f"(hi) : "l"(s))

__device__ double g_loss;
__device__ float g_enorm[NUM_EMB];
__device__ float g_xnorm[NPIX];

// 8-lane strided fp32 reduction matching LLVM-vectorized (VF=4, IC=2)
// fast-math reduce on the reference CPU.
__device__ __forceinline__ float reduce8_pattern(const float S[8]) {
    float t02 = __fadd_rn(__fadd_rn(S[0], S[4]), __fadd_rn(S[2], S[6]));
    float t13 = __fadd_rn(__fadd_rn(S[1], S[5]), __fadd_rn(S[3], S[7]));
    return __fadd_rn(t02, t13);
}

__global__ void vq_init_kernel(const float* __restrict__ emb) {
    int k = blockIdx.x * blockDim.x + threadIdx.x;
    if (k == 0 && blockIdx.x == 0) g_loss = 0.0;
    if (k < NUM_EMB) {
        const float* row = emb + (size_t)k * EMB_DIM;
        float S[8];
#pragma unroll
        for (int r = 0; r < 8; r++) S[r] = 0.f;
        for (int c = 0; c < EMB_DIM; c += 8) {
#pragma unroll
            for (int r = 0; r < 8; r++) {
                float v = row[c + r];
                S[r] = __fadd_rn(S[r], __fmul_rn(v, v));
            }
        }
        g_enorm[k] = reduce8_pattern(S);
    }
}

__global__ __launch_bounds__(256)
void vq_xnorm_kernel(const float* __restrict__ x) {
    int p = blockIdx.x * 256 + threadIdx.x;
    int b = p >> 12;
    int hw = p & (HW - 1);
    const float* xb = x + ((size_t)b * EMB_DIM) * HW + hw;
    float S[8];
#pragma unroll
    for (int r = 0; r < 8; r++) S[r] = 0.f;
    for (int c = 0; c < EMB_DIM; c += 8) {
#pragma unroll
        for (int r = 0; r < 8; r++) {
            float v = xb[(size_t)(c + r) * HW];
            S[r] = __fadd_rn(S[r], __fmul_rn(v, v));
        }
    }
    g_xnorm[p] = reduce8_pattern(S);
}

__global__ __launch_bounds__(THREADS)
void vq_main_kernel(const float* __restrict__ x,
                    const float* __restrict__ emb,
                    float* __restrict__ out) {
    __shared__ float xs[CC * MT];         // [c][p], stride 128: float4-readable
    __shared__ float es[NT * (CC + 1)];   // [k][c], stride 33: conflict-free
    __shared__ int s_idx[MT];
    __shared__ double s_loss[THREADS / 32];

    const int tid = threadIdx.x;
    const int tx = tid & 15;   // k coord: handles codes tx + 16*j
    const int ty = tid >> 4;   // p coord: handles pixels 8*ty .. 8*ty+7

    const int pix0 = blockIdx.x * MT;
    const int b = pix0 >> 12;
    const int hw0 = pix0 & (HW - 1);
    const float* xbase = x + ((size_t)b * EMB_DIM) * HW + hw0;

    float a_p[8];
#pragma unroll
    for (int i = 0; i < 8; i++) a_p[i] = g_xnorm[pix0 + 8 * ty + i];

    float best[8];
    int bidx[8];
#pragma unroll
    for (int i = 0; i < 8; i++) { best[i] = 3.4e38f; bidx[i] = 0; }

    for (int kt = 0; kt < NUM_EMB; kt += NT) {
        uint64_t acc2[4][8];   // f32x2 accumulators: pixel pair (2i2,2i2+1) x code j
#pragma unroll
        for (int i2 = 0; i2 < 4; i2++)
#pragma unroll
            for (int j = 0; j < 8; j++) acc2[i2][j] = 0ull;

        for (int cc = 0; cc < EMB_DIM; cc += CC) {
            __syncthreads();
            // x chunk: global coalesced over p, smem [c][p] contiguous writes
#pragma unroll
            for (int it = 0; it < (MT * CC) / THREADS; it++) {
                int i = tid + it * THREADS;
                int p = i & (MT - 1);
                int cr = i >> 7;
                xs[cr * MT + p] = xbase[(size_t)(cc + cr) * HW + p];
            }
            // e chunk: global coalesced over c, smem [k][c] stride 33
#pragma unroll
            for (int it = 0; it < (NT * CC) / THREADS; it++) {
                int i = tid + it * THREADS;
                int c = i & (CC - 1);
                int k = i >> 5;
                es[k * (CC + 1) + c] = emb[(size_t)(kt + k) * EMB_DIM + cc + c];
            }
            __syncthreads();
            // Strict sequential fp32 FMA chain over c ascending per (p,k);
            // packed across the pixel axis (independent lanes => bitwise
            // identical to scalar fmaf chain).
#pragma unroll 4
            for (int c = 0; c < CC; c++) {
                float4 xa = *(const float4*)&xs[c * MT + 8 * ty];
                float4 xb4 = *(const float4*)&xs[c * MT + 8 * ty + 4];
                uint64_t xv2[4];
                PACK2(xv2[0], xa.x, xa.y);
                PACK2(xv2[1], xa.z, xa.w);
                PACK2(xv2[2], xb4.x, xb4.y);
                PACK2(xv2[3], xb4.z, xb4.w);
#pragma unroll
                for (int j = 0; j < 8; j++) {
                    float ev = es[(tx + 16 * j) * (CC + 1) + c];
                    uint64_t ev2;
                    PACK2(ev2, ev, ev);
#pragma unroll
                    for (int i2 = 0; i2 < 4; i2++)
                        FMA2(acc2[i2][j], xv2[i2], ev2, acc2[i2][j]);
                }
            }
        }
        // Reference-rounded score: fl( fl(a - fl(2b)) + c ), k ascending per
        // thread => strict < is first-index tie-break within the partition.
#pragma unroll
        for (int j = 0; j < 8; j++) {
            int k = kt + tx + 16 * j;
            float en = g_enorm[k];
#pragma unroll
            for (int i2 = 0; i2 < 4; i2++) {
                float blo, bhi;
                UNPACK2(blo, bhi, acc2[i2][j]);
                float s0 = __fadd_rn(__fsub_rn(a_p[2 * i2], __fmul_rn(2.0f, blo)), en);
                float s1 = __fadd_rn(__fsub_rn(a_p[2 * i2 + 1], __fmul_rn(2.0f, bhi)), en);
                if (s0 < best[2 * i2]) { best[2 * i2] = s0; bidx[2 * i2] = k; }
                if (s1 < best[2 * i2 + 1]) { best[2 * i2 + 1] = s1; bidx[2 * i2 + 1] = k; }
            }
        }
    }

    // Reduce (score, idx) across the 16 tx-threads per pixel; ties -> lower k.
#pragma unroll
    for (int i = 0; i < 8; i++) {
        float s = best[i];
        int k = bidx[i];
#pragma unroll
        for (int off = 8; off > 0; off >>= 1) {
            float so = __shfl_down_sync(0xffffffffu, s, off, 16);
            int ko = __shfl_down_sync(0xffffffffu, k, off, 16);
            if (so < s || (so == s && ko < k)) { s = so; k = ko; }
        }
        if (tx == 0) s_idx[8 * ty + i] = k;
    }
    __syncthreads();

    // Writeback: coalesced NCHW stores; emb gather is L2-resident.
    float lsum = 0.f;
#pragma unroll 4
    for (int it = 0; it < (MT * EMB_DIM) / THREADS; it++) {
        int i = tid + it * THREADS;
        int p = i & (MT - 1);
        int c = i >> 7;
        int idx = s_idx[p];
        float q = __ldg(&emb[(size_t)idx * EMB_DIM + c]);
        float xv = xbase[(size_t)c * HW + p];
        out[1 + ((size_t)b * EMB_DIM + c) * HW + hw0 + p] = q;
        float d = q - xv;
        lsum = fmaf(d, d, lsum);
    }

#pragma unroll
    for (int off = 16; off > 0; off >>= 1)
        lsum += __shfl_down_sync(0xffffffffu, lsum, off);
    if ((tid & 31) == 0) s_loss[tid >> 5] = (double)lsum;
    __syncthreads();
    if (tid == 0) {
        double t = 0.0;
#pragma unroll
        for (int w = 0; w < THREADS / 32; w++) t += s_loss[w];
        atomicAdd(&g_loss, t);
    }
}

__global__ void vq_finalize_kernel(float* __restrict__ out) {
    out[0] = (float)(g_loss * (1.0625 / 16777216.0));
}

extern "C" void kernel_launch(void* const* d_in, const int* in_sizes, int n_in,
                              void* d_out, int out_size) {
    const float* x = (const float*)d_in[0];
    const float* emb = (const float*)d_in[1];
    float* out = (float*)d_out;

    vq_init_kernel<<<(NUM_EMB + 255) / 256, 256>>>(emb);
    vq_xnorm_kernel<<<NPIX / 256, 256>>>(x);
    vq_main_kernel<<<NPIX / MT, THREADS>>>(x, emb, out);
    vq_finalize_kernel<<<1, 1>>>(out);
}